// round 9
// baseline (speedup 1.0000x reference)
#include <cuda_runtime.h>
#include <cuda_bf16.h>
#include <math.h>
#include <cstdint>

#define NN 50000
#define SEQL 52
#define FIN 16
#define HD 128
#define H3 384
#define NE 800000
#define ET (NE + NN)
#define NEG 0.2f

// ---------------- static scratch ----------------
static __device__ float d_xp[(size_t)NN * HD];
static __device__ float d_as[NN];
static __device__ float d_ad[NN];
static __device__ unsigned short d_sph[(size_t)NN * HD];   // spatial hi bf16
static __device__ unsigned short d_spl[(size_t)NN * HD];   // spatial lo bf16
static __device__ float d_gi[(size_t)NN * H3];
static __device__ float d_h[(size_t)NN * HD];
static __device__ unsigned short d_hh[(size_t)NN * HD];    // h hi bf16
static __device__ unsigned short d_hl[(size_t)NN * HD];    // h lo bf16
static __device__ unsigned short d_wih_h[H3 * HD], d_wih_l[H3 * HD];
static __device__ unsigned short d_whh_h[H3 * HD], d_whh_l[H3 * HD];
static __device__ int   d_cnt[NN];
static __device__ int   d_rowptr[NN + 1];
static __device__ int   d_cur[NN];
static __device__ int   d_csrc[ET];

__device__ __forceinline__ uint32_t s2u(const void* p) {
    uint32_t a;
    asm("{ .reg .u64 t; cvta.to.shared.u64 t, %1; cvt.u32.u64 %0, t; }"
        : "=r"(a) : "l"(p));
    return a;
}

__device__ __forceinline__ void split_bf16(float v, unsigned short& hi,
                                           unsigned short& lo) {
    __nv_bfloat16 h = __float2bfloat16_rn(v);
    float rem = v - __bfloat162float(h);
    __nv_bfloat16 l = __float2bfloat16_rn(rem);
    hi = __bfloat16_as_ushort(h);
    lo = __bfloat16_as_ushort(l);
}

__device__ __forceinline__ void ldsm4(uint32_t* r, uint32_t addr) {
    asm volatile("ldmatrix.sync.aligned.m8n8.x4.shared.b16 {%0,%1,%2,%3}, [%4];"
                 : "=r"(r[0]), "=r"(r[1]), "=r"(r[2]), "=r"(r[3]) : "r"(addr));
}
__device__ __forceinline__ void mma16816(float* c, const uint32_t* a,
                                         uint32_t b0, uint32_t b1) {
    asm volatile(
        "mma.sync.aligned.m16n8k16.row.col.f32.bf16.bf16.f32 "
        "{%0,%1,%2,%3}, {%4,%5,%6,%7}, {%8,%9}, {%0,%1,%2,%3};"
        : "+f"(c[0]), "+f"(c[1]), "+f"(c[2]), "+f"(c[3])
        : "r"(a[0]), "r"(a[1]), "r"(a[2]), "r"(a[3]), "r"(b0), "r"(b1));
}

// ---------------- CSR build ----------------
__global__ void k_hist(const int* __restrict__ ei) {
    int idx = blockIdx.x * blockDim.x + threadIdx.x;
    if (idx < NE) {
        atomicAdd(&d_cnt[ei[NE + idx]], 1);
    } else if (idx < ET) {
        atomicAdd(&d_cnt[idx - NE], 1);
    }
}

__global__ void k_scan() {
    __shared__ int sh[1024];
    __shared__ int carry;
    int tid = threadIdx.x;
    if (tid == 0) carry = 0;
    __syncthreads();
    for (int base = 0; base < NN; base += 1024) {
        int v = (base + tid < NN) ? d_cnt[base + tid] : 0;
        sh[tid] = v;
        __syncthreads();
        for (int off = 1; off < 1024; off <<= 1) {
            int t2 = (tid >= off) ? sh[tid - off] : 0;
            __syncthreads();
            sh[tid] += t2;
            __syncthreads();
        }
        int inc = sh[tid];
        int ex = inc - v;
        if (base + tid < NN) {
            d_rowptr[base + tid] = carry + ex;
            d_cur[base + tid] = carry + ex;
        }
        int tot = sh[1023];
        __syncthreads();
        if (tid == 0) carry += tot;
        __syncthreads();
    }
    if (tid == 0) d_rowptr[NN] = carry;
}

__global__ void k_scatter(const int* __restrict__ ei) {
    int idx = blockIdx.x * blockDim.x + threadIdx.x;
    if (idx < NE) {
        int s = ei[idx];
        int d = ei[NE + idx];
        int p = atomicAdd(&d_cur[d], 1);
        d_csrc[p] = s;
    } else if (idx < ET) {
        int i = idx - NE;
        int p = atomicAdd(&d_cur[i], 1);
        d_csrc[p] = i;
    }
}

// ---------------- weight split to hi/lo bf16 ----------------
__global__ void k_wconv(const float* __restrict__ Wih,
                        const float* __restrict__ Whh) {
    int idx = blockIdx.x * blockDim.x + threadIdx.x;
    if (idx < H3 * HD) {
        split_bf16(Wih[idx], d_wih_h[idx], d_wih_l[idx]);
        split_bf16(Whh[idx], d_whh_h[idx], d_whh_l[idx]);
    }
}

// ---------------- xp = x_t @ Wg + attention dots ----------------
__global__ void k_xp(const float* __restrict__ x_t,
                     const float* __restrict__ Wg,
                     const float* __restrict__ att_s,
                     const float* __restrict__ att_d) {
    __shared__ float sWg[FIN * HD];
    __shared__ float sas[HD], sad[HD];
    __shared__ float sx[2][FIN];
    __shared__ float red_s[2][4], red_d[2][4];
    int tid = threadIdx.x;  // 256
    for (int i = tid; i < FIN * HD; i += 256) sWg[i] = Wg[i];
    if (tid < HD) { sas[tid] = att_s[tid]; sad[tid] = att_d[tid]; }
    int row = blockIdx.x * 2 + (tid / HD);
    int lr = tid / HD;
    int j = tid % HD;
    if (j < FIN && row < NN) sx[lr][j] = x_t[(size_t)row * FIN + j];
    __syncthreads();
    if (row >= NN) return;
    float acc = 0.f;
#pragma unroll
    for (int k = 0; k < FIN; k++) acc += sx[lr][k] * sWg[k * HD + j];
    d_xp[(size_t)row * HD + j] = acc;
    float vs = acc * sas[j];
    float vd = acc * sad[j];
#pragma unroll
    for (int o = 16; o > 0; o >>= 1) {
        vs += __shfl_down_sync(0xffffffffu, vs, o);
        vd += __shfl_down_sync(0xffffffffu, vd, o);
    }
    int lane = tid & 31;
    int w = (tid >> 5) & 3;
    if (lane == 0) { red_s[lr][w] = vs; red_d[lr][w] = vd; }
    __syncthreads();
    if (j == 0) {
        d_as[row] = red_s[lr][0] + red_s[lr][1] + red_s[lr][2] + red_s[lr][3];
        d_ad[row] = red_d[lr][0] + red_d[lr][1] + red_d[lr][2] + red_d[lr][3];
    }
}

// ---------------- GAT aggregate: warp/row online softmax; bf16 hi/lo out -----
__global__ void k_gat(const float* __restrict__ bias_g) {
    int warp = threadIdx.x >> 5, lane = threadIdx.x & 31;
    int row = blockIdx.x * 8 + warp;
    if (row >= NN) return;
    float ad = d_ad[row];
    int r0 = d_rowptr[row], r1 = d_rowptr[row + 1];
    float m = -1e30f, s = 0.f;
    float ax = 0.f, ay = 0.f, az = 0.f, aw = 0.f;
    int c = lane * 4;
    for (int e = r0; e < r1; e++) {
        int src = d_csrc[e];
        float ev = d_as[src] + ad;
        ev = (ev >= 0.f) ? ev : NEG * ev;
        float mn = fmaxf(m, ev);
        float sc = expf(m - mn);
        float w = expf(ev - mn);
        s = s * sc + w;
        float4 v = *(const float4*)(d_xp + (size_t)src * HD + c);
        ax = ax * sc + w * v.x;
        ay = ay * sc + w * v.y;
        az = az * sc + w * v.z;
        aw = aw * sc + w * v.w;
        m = mn;
    }
    float inv = 1.f / s;
    float4 b = *(const float4*)(bias_g + c);
    float4 o;
    o.x = fmaxf(ax * inv + b.x, 0.f);
    o.y = fmaxf(ay * inv + b.y, 0.f);
    o.z = fmaxf(az * inv + b.z, 0.f);
    o.w = fmaxf(aw * inv + b.w, 0.f);
    unsigned short h0, h1, h2, h3, l0, l1, l2, l3;
    split_bf16(o.x, h0, l0);
    split_bf16(o.y, h1, l1);
    split_bf16(o.z, h2, l2);
    split_bf16(o.w, h3, l3);
    size_t off = (size_t)row * HD + c;
    uint2 ph = make_uint2((uint32_t)h0 | ((uint32_t)h1 << 16),
                          (uint32_t)h2 | ((uint32_t)h3 << 16));
    uint2 pl = make_uint2((uint32_t)l0 | ((uint32_t)l1 << 16),
                          (uint32_t)l2 | ((uint32_t)l3 << 16));
    *(uint2*)(d_sph + off) = ph;
    *(uint2*)(d_spl + off) = pl;
}

// ---------------- HMMA split-bf16 spatial GEMM: gi = sp @ Wih^T + b_ih -------
#define TSTRIDE 272                 // padded row stride in bytes
#define TILE_B (128 * TSTRIDE)      // 34816
#define SM_BIAS 0
#define SM_T0 512
#define MMA_SMEM (512 + 4 * TILE_B)

__global__ void __launch_bounds__(256, 1)
k_mma(const uint4* __restrict__ Ah, const uint4* __restrict__ Al,
      const uint4* __restrict__ Bh, const uint4* __restrict__ Bl,
      const float* __restrict__ bias, float* __restrict__ C, int M) {
    extern __shared__ char smem[];
    uint32_t sb = s2u(smem);
    int tid = threadIdx.x, wid = tid >> 5, lane = tid & 31;
    int m0 = blockIdx.x * 128, cb = blockIdx.y;

    if (tid < 128) ((float*)(smem + SM_BIAS))[tid] = bias[cb * 128 + tid];

    for (int idx = tid; idx < 2048; idx += 256) {
        int r = idx >> 4, q = idx & 15;
        int gm = m0 + r;
        uint4 vh = make_uint4(0, 0, 0, 0), vl = make_uint4(0, 0, 0, 0);
        if (gm < M) {
            vh = Ah[(size_t)gm * 16 + q];
            vl = Al[(size_t)gm * 16 + q];
        }
        char* dst = smem + SM_T0 + r * TSTRIDE + q * 16;
        *(uint4*)dst = vh;
        *(uint4*)(dst + TILE_B) = vl;
        int gb = cb * 128 + r;
        uint4 wh = Bh[(size_t)gb * 16 + q];
        uint4 wl = Bl[(size_t)gb * 16 + q];
        *(uint4*)(dst + 2 * TILE_B) = wh;
        *(uint4*)(dst + 3 * TILE_B) = wl;
    }
    __syncthreads();

    int warp_m = (wid >> 2) * 64;
    int warp_n = (wid & 3) * 32;

    float acc[4][4][4];
#pragma unroll
    for (int i = 0; i < 4; i++)
#pragma unroll
        for (int j = 0; j < 4; j++)
#pragma unroll
            for (int k = 0; k < 4; k++) acc[i][j][k] = 0.f;

    uint32_t aAddr[4], bAddr[2];
    {
        int rowA = (lane & 7) + ((lane >> 3) & 1) * 8;
        int kofA = ((lane >> 4) & 1) * 16;
#pragma unroll
        for (int mi = 0; mi < 4; mi++)
            aAddr[mi] = sb + SM_T0 +
                        (warp_m + mi * 16 + rowA) * TSTRIDE + kofA;
        int rowB = (lane & 7) + ((lane >> 4) & 1) * 8;
        int kofB = ((lane >> 3) & 1) * 16;
#pragma unroll
        for (int p = 0; p < 2; p++)
            bAddr[p] = sb + SM_T0 + 2 * TILE_B +
                       (warp_n + p * 16 + rowB) * TSTRIDE + kofB;
    }

#pragma unroll
    for (int ks = 0; ks < 8; ks++) {
        uint32_t ah[4][4], al[4][4], bh[2][4], bl[2][4];
#pragma unroll
        for (int mi = 0; mi < 4; mi++) {
            uint32_t ad = aAddr[mi] + ks * 32;
            ldsm4(ah[mi], ad);
            ldsm4(al[mi], ad + TILE_B);
        }
#pragma unroll
        for (int p = 0; p < 2; p++) {
            uint32_t bd = bAddr[p] + ks * 32;
            ldsm4(bh[p], bd);
            ldsm4(bl[p], bd + TILE_B);
        }
#pragma unroll
        for (int mi = 0; mi < 4; mi++) {
#pragma unroll
            for (int p = 0; p < 2; p++) {
#pragma unroll
                for (int sub = 0; sub < 2; sub++) {
                    float* c = acc[mi][p * 2 + sub];
                    uint32_t b0 = bh[p][sub * 2 + 0], b1 = bh[p][sub * 2 + 1];
                    mma16816(c, ah[mi], b0, b1);
                    mma16816(c, al[mi], b0, b1);
                    mma16816(c, ah[mi], bl[p][sub * 2 + 0],
                             bl[p][sub * 2 + 1]);
                }
            }
        }
    }

    const float* sbias = (const float*)(smem + SM_BIAS);
    int trow = lane >> 2, tcol = (lane & 3) * 2;
#pragma unroll
    for (int mi = 0; mi < 4; mi++) {
        int gm0 = m0 + warp_m + mi * 16 + trow;
#pragma unroll
        for (int nj = 0; nj < 4; nj++) {
            int nc = warp_n + nj * 8 + tcol;
            int gc = cb * 128 + nc;
            float b0 = sbias[nc], b1 = sbias[nc + 1];
            if (gm0 < M) {
                float2 o = make_float2(acc[mi][nj][0] + b0,
                                       acc[mi][nj][1] + b1);
                *(float2*)(C + (size_t)gm0 * H3 + gc) = o;
            }
            if (gm0 + 8 < M) {
                float2 o = make_float2(acc[mi][nj][2] + b0,
                                       acc[mi][nj][3] + b1);
                *(float2*)(C + (size_t)(gm0 + 8) * H3 + gc) = o;
            }
        }
    }
}

// ---------------- fused hidden GEMM + GRU: h = GRU(gi, h) --------------------
// 64 rows/CTA, loop over 3 gate chunks; r,z kept in registers; gi read in
// epilogue (L2-resident); single GEMM -> no register spill.
#define HA_TILE (64 * TSTRIDE)               // 17408
#define HB_TILE (128 * TSTRIDE)              // 34816
#define HS_B0   (2 * HA_TILE)                // 34816
#define HGRU_SMEM (HS_B0 + 2 * HB_TILE)      // 104448

__global__ void __launch_bounds__(256, 1)
k_hgru(const uint4* __restrict__ Ah_h, const uint4* __restrict__ Ah_l,
       const uint4* __restrict__ Whh_h, const uint4* __restrict__ Whh_l,
       const float* __restrict__ gi, const float* __restrict__ b_hh,
       float* __restrict__ Hout, unsigned short* __restrict__ Hh,
       unsigned short* __restrict__ Hl) {
    extern __shared__ char smem[];
    uint32_t sb = s2u(smem);
    int tid = threadIdx.x, wid = tid >> 5, lane = tid & 31;
    int m0 = blockIdx.x * 64;

    // A tiles: h hi/lo, 64 rows x 128 bf16
    for (int idx = tid; idx < 1024; idx += 256) {
        int r = idx >> 4, q = idx & 15;
        int gm = m0 + r;
        uint4 vh = make_uint4(0, 0, 0, 0), vl = vh;
        if (gm < NN) {
            size_t go = (size_t)gm * 16 + q;
            vh = Ah_h[go];
            vl = Ah_l[go];
        }
        char* dst = smem + r * TSTRIDE + q * 16;
        *(uint4*)dst = vh;
        *(uint4*)(dst + HA_TILE) = vl;
    }

    int warp_m = (wid >> 2) * 32;
    int warp_n = (wid & 3) * 32;
    int rowA = (lane & 7) + ((lane >> 3) & 1) * 8;
    int kofA = ((lane >> 4) & 1) * 16;
    int rowB = (lane & 7) + ((lane >> 4) & 1) * 8;
    int kofB = ((lane >> 3) & 1) * 16;
    uint32_t aOff[2], bOff[2];
#pragma unroll
    for (int mi = 0; mi < 2; mi++)
        aOff[mi] = sb + (warp_m + mi * 16 + rowA) * TSTRIDE + kofA;
#pragma unroll
    for (int p = 0; p < 2; p++)
        bOff[p] = sb + HS_B0 + (warp_n + p * 16 + rowB) * TSTRIDE + kofB;

    int trow = lane >> 2, tcol = (lane & 3) * 2;

    float r_reg[2][4][4], z_reg[2][4][4];

    for (int cb = 0; cb < 3; cb++) {
        __syncthreads();   // prior chunk's MMA reads done (and A stores @cb=0)
        for (int idx = tid; idx < 2048; idx += 256) {
            int r = idx >> 4, q = idx & 15;
            size_t go = (size_t)(cb * 128 + r) * 16 + q;
            char* dst = smem + HS_B0 + r * TSTRIDE + q * 16;
            *(uint4*)dst = Whh_h[go];
            *(uint4*)(dst + HB_TILE) = Whh_l[go];
        }
        __syncthreads();

        float acc[2][4][4];
#pragma unroll
        for (int i = 0; i < 2; i++)
#pragma unroll
            for (int j = 0; j < 4; j++)
#pragma unroll
                for (int k = 0; k < 4; k++) acc[i][j][k] = 0.f;

#pragma unroll
        for (int ks = 0; ks < 8; ks++) {
            uint32_t ah[2][4], al[2][4], bh[2][4], bl[2][4];
#pragma unroll
            for (int mi = 0; mi < 2; mi++) {
                uint32_t ad = aOff[mi] + ks * 32;
                ldsm4(ah[mi], ad);
                ldsm4(al[mi], ad + HA_TILE);
            }
#pragma unroll
            for (int p = 0; p < 2; p++) {
                uint32_t bd = bOff[p] + ks * 32;
                ldsm4(bh[p], bd);
                ldsm4(bl[p], bd + HB_TILE);
            }
#pragma unroll
            for (int mi = 0; mi < 2; mi++)
#pragma unroll
                for (int p = 0; p < 2; p++)
#pragma unroll
                    for (int sub = 0; sub < 2; sub++) {
                        float* c = acc[mi][p * 2 + sub];
                        uint32_t b0 = bh[p][sub * 2], b1 = bh[p][sub * 2 + 1];
                        mma16816(c, ah[mi], b0, b1);
                        mma16816(c, al[mi], b0, b1);
                        mma16816(c, ah[mi], bl[p][sub * 2], bl[p][sub * 2 + 1]);
                    }
        }

        // per-chunk gate epilogue
#pragma unroll
        for (int mi = 0; mi < 2; mi++) {
#pragma unroll
            for (int nj = 0; nj < 4; nj++) {
                int nc = warp_n + nj * 8 + tcol;
                int gc = cb * 128 + nc;
                float2 bh2 = *(const float2*)(b_hh + gc);
#pragma unroll
                for (int half = 0; half < 2; half++) {
                    int gm = m0 + warp_m + mi * 16 + trow + half * 8;
                    if (gm >= NN) continue;
                    float2 giv = *(const float2*)(gi + (size_t)gm * H3 + gc);
                    float gh0 = acc[mi][nj][half * 2 + 0] + bh2.x;
                    float gh1 = acc[mi][nj][half * 2 + 1] + bh2.y;
                    if (cb == 0) {
                        r_reg[mi][nj][half * 2 + 0] =
                            1.f / (1.f + expf(-(giv.x + gh0)));
                        r_reg[mi][nj][half * 2 + 1] =
                            1.f / (1.f + expf(-(giv.y + gh1)));
                    } else if (cb == 1) {
                        z_reg[mi][nj][half * 2 + 0] =
                            1.f / (1.f + expf(-(giv.x + gh0)));
                        z_reg[mi][nj][half * 2 + 1] =
                            1.f / (1.f + expf(-(giv.y + gh1)));
                    } else {
                        float r0 = r_reg[mi][nj][half * 2 + 0];
                        float r1 = r_reg[mi][nj][half * 2 + 1];
                        float z0 = z_reg[mi][nj][half * 2 + 0];
                        float z1 = z_reg[mi][nj][half * 2 + 1];
                        float n0 = tanhf(giv.x + r0 * gh0);
                        float n1 = tanhf(giv.y + r1 * gh1);
                        size_t ho = (size_t)gm * HD + nc;
                        float2 hp = *(const float2*)(Hout + ho);
                        float o0 = (1.f - z0) * n0 + z0 * hp.x;
                        float o1 = (1.f - z1) * n1 + z1 * hp.y;
                        *(float2*)(Hout + ho) = make_float2(o0, o1);
                        unsigned short hh0, hl0, hh1, hl1;
                        split_bf16(o0, hh0, hl0);
                        split_bf16(o1, hh1, hl1);
                        *(uint32_t*)(Hh + ho) =
                            (uint32_t)hh0 | ((uint32_t)hh1 << 16);
                        *(uint32_t*)(Hl + ho) =
                            (uint32_t)hl0 | ((uint32_t)hl1 << 16);
                    }
                }
            }
        }
    }
}

// ---------------- final fc ----------------
__global__ void k_fc(const float* __restrict__ Wfc,
                     const float* __restrict__ bfc,
                     float* __restrict__ out) {
    int warp = threadIdx.x >> 5, lane = threadIdx.x & 31;
    int row = blockIdx.x * 8 + warp;
    if (row >= NN) return;
    float4 hv = *(const float4*)(d_h + (size_t)row * HD + lane * 4);
    float4 wv = *(const float4*)(Wfc + lane * 4);
    float v = hv.x * wv.x + hv.y * wv.y + hv.z * wv.z + hv.w * wv.w;
#pragma unroll
    for (int o = 16; o > 0; o >>= 1) v += __shfl_down_sync(0xffffffffu, v, o);
    if (lane == 0) out[row] = v + bfc[0];
}

// ---------------- launch ----------------
extern "C" void kernel_launch(void* const* d_in, const int* in_sizes, int n_in,
                              void* d_out, int out_size) {
    const float* x_seq   = (const float*)d_in[0];
    const int*   ei      = (const int*)d_in[1];
    const float* Wg      = (const float*)d_in[2];
    const float* att_src = (const float*)d_in[3];
    const float* att_dst = (const float*)d_in[4];
    const float* bias_g  = (const float*)d_in[5];
    const float* W_ih    = (const float*)d_in[6];
    const float* W_hh    = (const float*)d_in[7];
    const float* b_ih    = (const float*)d_in[8];
    const float* b_hh    = (const float*)d_in[9];
    const float* W_fc    = (const float*)d_in[10];
    const float* b_fc    = (const float*)d_in[11];
    float* out = (float*)d_out;

    void *p_cnt, *p_h, *p_hh, *p_hl, *p_sph, *p_spl, *p_gi;
    void *p_wih_h, *p_wih_l, *p_whh_h, *p_whh_l;
    cudaGetSymbolAddress(&p_cnt, d_cnt);
    cudaGetSymbolAddress(&p_h, d_h);
    cudaGetSymbolAddress(&p_hh, d_hh);
    cudaGetSymbolAddress(&p_hl, d_hl);
    cudaGetSymbolAddress(&p_sph, d_sph);
    cudaGetSymbolAddress(&p_spl, d_spl);
    cudaGetSymbolAddress(&p_gi, d_gi);
    cudaGetSymbolAddress(&p_wih_h, d_wih_h);
    cudaGetSymbolAddress(&p_wih_l, d_wih_l);
    cudaGetSymbolAddress(&p_whh_h, d_whh_h);
    cudaGetSymbolAddress(&p_whh_l, d_whh_l);

    cudaFuncSetAttribute(k_mma, cudaFuncAttributeMaxDynamicSharedMemorySize,
                         MMA_SMEM);
    cudaFuncSetAttribute(k_hgru, cudaFuncAttributeMaxDynamicSharedMemorySize,
                         HGRU_SMEM);

    cudaMemsetAsync(p_cnt, 0, NN * sizeof(int));
    cudaMemsetAsync(p_h, 0, (size_t)NN * HD * sizeof(float));
    cudaMemsetAsync(p_hh, 0, (size_t)NN * HD * sizeof(unsigned short));
    cudaMemsetAsync(p_hl, 0, (size_t)NN * HD * sizeof(unsigned short));

    k_wconv<<<(H3 * HD + 255) / 256, 256>>>(W_ih, W_hh);
    k_hist<<<(ET + 255) / 256, 256>>>(ei);
    k_scan<<<1, 1024>>>();
    k_scatter<<<(ET + 255) / 256, 256>>>(ei);

    dim3 mgrid((NN + 127) / 128, 3);
    int hgrid = (NN + 63) / 64;
    for (int t = 0; t < SEQL; t++) {
        k_xp<<<(NN + 1) / 2, 256>>>(x_seq + (size_t)t * NN * FIN, Wg,
                                    att_src, att_dst);
        k_gat<<<(NN + 7) / 8, 256>>>(bias_g);
        k_mma<<<mgrid, 256, MMA_SMEM>>>(
            (const uint4*)p_sph, (const uint4*)p_spl,
            (const uint4*)p_wih_h, (const uint4*)p_wih_l,
            b_ih, (float*)p_gi, NN);
        k_hgru<<<hgrid, 256, HGRU_SMEM>>>(
            (const uint4*)p_hh, (const uint4*)p_hl,
            (const uint4*)p_whh_h, (const uint4*)p_whh_l,
            (const float*)p_gi, b_hh,
            (float*)p_h, (unsigned short*)p_hh, (unsigned short*)p_hl);
    }

    k_fc<<<(NN + 7) / 8, 256>>>(W_fc, b_fc, out);
}

// round 10
// speedup vs baseline: 1.3816x; 1.3816x over previous
#include <cuda_runtime.h>
#include <cuda_bf16.h>
#include <math.h>
#include <cstdint>

#define NN 50000
#define SEQL 52
#define FIN 16
#define HD 128
#define H3 384
#define NE 800000
#define ET (NE + NN)
#define NEG 0.2f

// ---------------- static scratch ----------------
static __device__ float d_xp[(size_t)NN * HD];
static __device__ float d_as[NN];
static __device__ float d_ad[NN];
static __device__ unsigned short d_sph[(size_t)NN * HD];   // spatial hi bf16
static __device__ unsigned short d_spl[(size_t)NN * HD];   // spatial lo bf16
static __device__ float d_gi[(size_t)NN * H3];
static __device__ float d_gh[(size_t)NN * H3];
static __device__ float d_h[(size_t)NN * HD];
static __device__ unsigned short d_hh[(size_t)NN * HD];    // h hi bf16
static __device__ unsigned short d_hl[(size_t)NN * HD];    // h lo bf16
static __device__ unsigned short d_wih_h[H3 * HD], d_wih_l[H3 * HD];
static __device__ unsigned short d_whh_h[H3 * HD], d_whh_l[H3 * HD];
static __device__ int   d_cnt[NN];
static __device__ int   d_rowptr[NN + 1];
static __device__ int   d_cur[NN];
static __device__ int   d_csrc[ET];

__device__ __forceinline__ uint32_t s2u(const void* p) {
    uint32_t a;
    asm("{ .reg .u64 t; cvta.to.shared.u64 t, %1; cvt.u32.u64 %0, t; }"
        : "=r"(a) : "l"(p));
    return a;
}

__device__ __forceinline__ void split_bf16(float v, unsigned short& hi,
                                           unsigned short& lo) {
    __nv_bfloat16 h = __float2bfloat16_rn(v);
    float rem = v - __bfloat162float(h);
    __nv_bfloat16 l = __float2bfloat16_rn(rem);
    hi = __bfloat16_as_ushort(h);
    lo = __bfloat16_as_ushort(l);
}

__device__ __forceinline__ void ldsm4(uint32_t* r, uint32_t addr) {
    asm volatile("ldmatrix.sync.aligned.m8n8.x4.shared.b16 {%0,%1,%2,%3}, [%4];"
                 : "=r"(r[0]), "=r"(r[1]), "=r"(r[2]), "=r"(r[3]) : "r"(addr));
}
__device__ __forceinline__ void mma16816(float* c, const uint32_t* a,
                                         uint32_t b0, uint32_t b1) {
    asm volatile(
        "mma.sync.aligned.m16n8k16.row.col.f32.bf16.bf16.f32 "
        "{%0,%1,%2,%3}, {%4,%5,%6,%7}, {%8,%9}, {%0,%1,%2,%3};"
        : "+f"(c[0]), "+f"(c[1]), "+f"(c[2]), "+f"(c[3])
        : "r"(a[0]), "r"(a[1]), "r"(a[2]), "r"(a[3]), "r"(b0), "r"(b1));
}

// ---------------- CSR build ----------------
__global__ void k_hist(const int* __restrict__ ei) {
    int idx = blockIdx.x * blockDim.x + threadIdx.x;
    if (idx < NE) {
        atomicAdd(&d_cnt[ei[NE + idx]], 1);
    } else if (idx < ET) {
        atomicAdd(&d_cnt[idx - NE], 1);
    }
}

__global__ void k_scan() {
    __shared__ int sh[1024];
    __shared__ int carry;
    int tid = threadIdx.x;
    if (tid == 0) carry = 0;
    __syncthreads();
    for (int base = 0; base < NN; base += 1024) {
        int v = (base + tid < NN) ? d_cnt[base + tid] : 0;
        sh[tid] = v;
        __syncthreads();
        for (int off = 1; off < 1024; off <<= 1) {
            int t2 = (tid >= off) ? sh[tid - off] : 0;
            __syncthreads();
            sh[tid] += t2;
            __syncthreads();
        }
        int inc = sh[tid];
        int ex = inc - v;
        if (base + tid < NN) {
            d_rowptr[base + tid] = carry + ex;
            d_cur[base + tid] = carry + ex;
        }
        int tot = sh[1023];
        __syncthreads();
        if (tid == 0) carry += tot;
        __syncthreads();
    }
    if (tid == 0) d_rowptr[NN] = carry;
}

__global__ void k_scatter(const int* __restrict__ ei) {
    int idx = blockIdx.x * blockDim.x + threadIdx.x;
    if (idx < NE) {
        int s = ei[idx];
        int d = ei[NE + idx];
        int p = atomicAdd(&d_cur[d], 1);
        d_csrc[p] = s;
    } else if (idx < ET) {
        int i = idx - NE;
        int p = atomicAdd(&d_cur[i], 1);
        d_csrc[p] = i;
    }
}

// ---------------- weight split to hi/lo bf16 ----------------
__global__ void k_wconv(const float* __restrict__ Wih,
                        const float* __restrict__ Whh) {
    int idx = blockIdx.x * blockDim.x + threadIdx.x;
    if (idx < H3 * HD) {
        split_bf16(Wih[idx], d_wih_h[idx], d_wih_l[idx]);
        split_bf16(Whh[idx], d_whh_h[idx], d_whh_l[idx]);
    }
}

// ---------------- xp = x_t @ Wg + attention dots ----------------
__global__ void k_xp(const float* __restrict__ x_t,
                     const float* __restrict__ Wg,
                     const float* __restrict__ att_s,
                     const float* __restrict__ att_d) {
    __shared__ float sWg[FIN * HD];
    __shared__ float sas[HD], sad[HD];
    __shared__ float sx[2][FIN];
    __shared__ float red_s[2][4], red_d[2][4];
    int tid = threadIdx.x;  // 256
    for (int i = tid; i < FIN * HD; i += 256) sWg[i] = Wg[i];
    if (tid < HD) { sas[tid] = att_s[tid]; sad[tid] = att_d[tid]; }
    int row = blockIdx.x * 2 + (tid / HD);
    int lr = tid / HD;
    int j = tid % HD;
    if (j < FIN && row < NN) sx[lr][j] = x_t[(size_t)row * FIN + j];
    __syncthreads();
    if (row >= NN) return;
    float acc = 0.f;
#pragma unroll
    for (int k = 0; k < FIN; k++) acc += sx[lr][k] * sWg[k * HD + j];
    d_xp[(size_t)row * HD + j] = acc;
    float vs = acc * sas[j];
    float vd = acc * sad[j];
#pragma unroll
    for (int o = 16; o > 0; o >>= 1) {
        vs += __shfl_down_sync(0xffffffffu, vs, o);
        vd += __shfl_down_sync(0xffffffffu, vd, o);
    }
    int lane = tid & 31;
    int w = (tid >> 5) & 3;
    if (lane == 0) { red_s[lr][w] = vs; red_d[lr][w] = vd; }
    __syncthreads();
    if (j == 0) {
        d_as[row] = red_s[lr][0] + red_s[lr][1] + red_s[lr][2] + red_s[lr][3];
        d_ad[row] = red_d[lr][0] + red_d[lr][1] + red_d[lr][2] + red_d[lr][3];
    }
}

// ---------------- GAT aggregate: warp/row softmax (scores bounded, no max) ---
__global__ void k_gat(const float* __restrict__ bias_g) {
    int warp = threadIdx.x >> 5, lane = threadIdx.x & 31;
    int row = blockIdx.x * 8 + warp;
    if (row >= NN) return;
    float ad = d_ad[row];
    int r0 = d_rowptr[row], r1 = d_rowptr[row + 1];
    float s = 0.f;
    float ax = 0.f, ay = 0.f, az = 0.f, aw = 0.f;
    int c = lane * 4;
    for (int e = r0; e < r1; e++) {
        int src = d_csrc[e];
        float ev = d_as[src] + ad;
        ev = (ev >= 0.f) ? ev : NEG * ev;
        float w = expf(ev);
        s += w;
        float4 v = *(const float4*)(d_xp + (size_t)src * HD + c);
        ax += w * v.x;
        ay += w * v.y;
        az += w * v.z;
        aw += w * v.w;
    }
    float inv = 1.f / s;
    float4 b = *(const float4*)(bias_g + c);
    float4 o;
    o.x = fmaxf(ax * inv + b.x, 0.f);
    o.y = fmaxf(ay * inv + b.y, 0.f);
    o.z = fmaxf(az * inv + b.z, 0.f);
    o.w = fmaxf(aw * inv + b.w, 0.f);
    unsigned short h0, h1, h2, h3, l0, l1, l2, l3;
    split_bf16(o.x, h0, l0);
    split_bf16(o.y, h1, l1);
    split_bf16(o.z, h2, l2);
    split_bf16(o.w, h3, l3);
    size_t off = (size_t)row * HD + c;
    uint2 ph = make_uint2((uint32_t)h0 | ((uint32_t)h1 << 16),
                          (uint32_t)h2 | ((uint32_t)h3 << 16));
    uint2 pl = make_uint2((uint32_t)l0 | ((uint32_t)l1 << 16),
                          (uint32_t)l2 | ((uint32_t)l3 << 16));
    *(uint2*)(d_sph + off) = ph;
    *(uint2*)(d_spl + off) = pl;
}

// ---- merged HMMA split-bf16 GEMMs: z=0: gi=sp@Wih^T+b_ih, z=1: gh=h@Whh^T ---
#define TSTRIDE 272                 // padded row stride in bytes
#define TILE_B (128 * TSTRIDE)      // 34816
#define SM_BIAS 0
#define SM_T0 512
#define MMA_SMEM (512 + 4 * TILE_B)

__global__ void __launch_bounds__(256, 1)
k_mma(const uint4* __restrict__ A0h, const uint4* __restrict__ A0l,
      const uint4* __restrict__ B0h, const uint4* __restrict__ B0l,
      const float* __restrict__ bias0, float* __restrict__ C0,
      const uint4* __restrict__ A1h, const uint4* __restrict__ A1l,
      const uint4* __restrict__ B1h, const uint4* __restrict__ B1l,
      const float* __restrict__ bias1, float* __restrict__ C1, int M) {
    extern __shared__ char smem[];
    uint32_t sb = s2u(smem);
    int tid = threadIdx.x, wid = tid >> 5, lane = tid & 31;
    int m0 = blockIdx.x * 128, cb = blockIdx.y;
    int gz = blockIdx.z;
    const uint4* Ah = gz ? A1h : A0h;
    const uint4* Al = gz ? A1l : A0l;
    const uint4* Bh = gz ? B1h : B0h;
    const uint4* Bl = gz ? B1l : B0l;
    const float* bias = gz ? bias1 : bias0;
    float* C = gz ? C1 : C0;

    if (tid < 128) ((float*)(smem + SM_BIAS))[tid] = bias[cb * 128 + tid];

    for (int idx = tid; idx < 2048; idx += 256) {
        int r = idx >> 4, q = idx & 15;
        int gm = m0 + r;
        uint4 vh = make_uint4(0, 0, 0, 0), vl = make_uint4(0, 0, 0, 0);
        if (gm < M) {
            vh = Ah[(size_t)gm * 16 + q];
            vl = Al[(size_t)gm * 16 + q];
        }
        char* dst = smem + SM_T0 + r * TSTRIDE + q * 16;
        *(uint4*)dst = vh;
        *(uint4*)(dst + TILE_B) = vl;
        int gb = cb * 128 + r;
        uint4 wh = Bh[(size_t)gb * 16 + q];
        uint4 wl = Bl[(size_t)gb * 16 + q];
        *(uint4*)(dst + 2 * TILE_B) = wh;
        *(uint4*)(dst + 3 * TILE_B) = wl;
    }
    __syncthreads();

    int warp_m = (wid >> 2) * 64;
    int warp_n = (wid & 3) * 32;

    float acc[4][4][4];
#pragma unroll
    for (int i = 0; i < 4; i++)
#pragma unroll
        for (int j = 0; j < 4; j++)
#pragma unroll
            for (int k = 0; k < 4; k++) acc[i][j][k] = 0.f;

    uint32_t aAddr[4], bAddr[2];
    {
        int rowA = (lane & 7) + ((lane >> 3) & 1) * 8;
        int kofA = ((lane >> 4) & 1) * 16;
#pragma unroll
        for (int mi = 0; mi < 4; mi++)
            aAddr[mi] = sb + SM_T0 +
                        (warp_m + mi * 16 + rowA) * TSTRIDE + kofA;
        int rowB = (lane & 7) + ((lane >> 4) & 1) * 8;
        int kofB = ((lane >> 3) & 1) * 16;
#pragma unroll
        for (int p = 0; p < 2; p++)
            bAddr[p] = sb + SM_T0 + 2 * TILE_B +
                       (warp_n + p * 16 + rowB) * TSTRIDE + kofB;
    }

#pragma unroll
    for (int ks = 0; ks < 8; ks++) {
        uint32_t ah[4][4], al[4][4], bh[2][4], bl[2][4];
#pragma unroll
        for (int mi = 0; mi < 4; mi++) {
            uint32_t ad = aAddr[mi] + ks * 32;
            ldsm4(ah[mi], ad);
            ldsm4(al[mi], ad + TILE_B);
        }
#pragma unroll
        for (int p = 0; p < 2; p++) {
            uint32_t bd = bAddr[p] + ks * 32;
            ldsm4(bh[p], bd);
            ldsm4(bl[p], bd + TILE_B);
        }
#pragma unroll
        for (int mi = 0; mi < 4; mi++) {
#pragma unroll
            for (int p = 0; p < 2; p++) {
#pragma unroll
                for (int sub = 0; sub < 2; sub++) {
                    float* c = acc[mi][p * 2 + sub];
                    uint32_t b0 = bh[p][sub * 2 + 0], b1 = bh[p][sub * 2 + 1];
                    mma16816(c, ah[mi], b0, b1);
                    mma16816(c, al[mi], b0, b1);
                    mma16816(c, ah[mi], bl[p][sub * 2 + 0],
                             bl[p][sub * 2 + 1]);
                }
            }
        }
    }

    const float* sbias = (const float*)(smem + SM_BIAS);
    int trow = lane >> 2, tcol = (lane & 3) * 2;
#pragma unroll
    for (int mi = 0; mi < 4; mi++) {
        int gm0 = m0 + warp_m + mi * 16 + trow;
#pragma unroll
        for (int nj = 0; nj < 4; nj++) {
            int nc = warp_n + nj * 8 + tcol;
            int gc = cb * 128 + nc;
            float b0 = sbias[nc], b1 = sbias[nc + 1];
            if (gm0 < M) {
                float2 o = make_float2(acc[mi][nj][0] + b0,
                                       acc[mi][nj][1] + b1);
                *(float2*)(C + (size_t)gm0 * H3 + gc) = o;
            }
            if (gm0 + 8 < M) {
                float2 o = make_float2(acc[mi][nj][2] + b0,
                                       acc[mi][nj][3] + b1);
                *(float2*)(C + (size_t)(gm0 + 8) * H3 + gc) = o;
            }
        }
    }
}

// ---------------- GRU elementwise update; streaming gi/gh reads --------------
__global__ void k_gru() {
    int idx = blockIdx.x * blockDim.x + threadIdx.x;   // over NN*HD/4
    if (idx >= NN * HD / 4) return;
    int i = idx / (HD / 4), j4 = (idx % (HD / 4)) * 4;
    const float4* gi = (const float4*)(d_gi + (size_t)i * H3 + j4);
    const float4* gh = (const float4*)(d_gh + (size_t)i * H3 + j4);
    float4 gir = __ldcs(gi);
    float4 giz = __ldcs((const float4*)((const float*)gi + HD));
    float4 gin = __ldcs((const float4*)((const float*)gi + 2 * HD));
    float4 ghr = __ldcs(gh);
    float4 ghz = __ldcs((const float4*)((const float*)gh + HD));
    float4 ghn = __ldcs((const float4*)((const float*)gh + 2 * HD));
    size_t hoff = (size_t)i * HD + j4;
    float4 h = *(const float4*)(d_h + hoff);
    float4 o;
#define GRU1(c)                                                   \
    {                                                             \
        float r = 1.f / (1.f + expf(-(gir.c + ghr.c)));           \
        float z = 1.f / (1.f + expf(-(giz.c + ghz.c)));           \
        float n = tanhf(gin.c + r * ghn.c);                       \
        o.c = (1.f - z) * n + z * h.c;                            \
    }
    GRU1(x) GRU1(y) GRU1(z) GRU1(w)
#undef GRU1
    *(float4*)(d_h + hoff) = o;
    unsigned short h0, h1, h2, h3, l0, l1, l2, l3;
    split_bf16(o.x, h0, l0);
    split_bf16(o.y, h1, l1);
    split_bf16(o.z, h2, l2);
    split_bf16(o.w, h3, l3);
    uint2 ph = make_uint2((uint32_t)h0 | ((uint32_t)h1 << 16),
                          (uint32_t)h2 | ((uint32_t)h3 << 16));
    uint2 pl = make_uint2((uint32_t)l0 | ((uint32_t)l1 << 16),
                          (uint32_t)l2 | ((uint32_t)l3 << 16));
    *(uint2*)(d_hh + hoff) = ph;
    *(uint2*)(d_hl + hoff) = pl;
}

// ---------------- final fc ----------------
__global__ void k_fc(const float* __restrict__ Wfc,
                     const float* __restrict__ bfc,
                     float* __restrict__ out) {
    int warp = threadIdx.x >> 5, lane = threadIdx.x & 31;
    int row = blockIdx.x * 8 + warp;
    if (row >= NN) return;
    float4 hv = *(const float4*)(d_h + (size_t)row * HD + lane * 4);
    float4 wv = *(const float4*)(Wfc + lane * 4);
    float v = hv.x * wv.x + hv.y * wv.y + hv.z * wv.z + hv.w * wv.w;
#pragma unroll
    for (int o = 16; o > 0; o >>= 1) v += __shfl_down_sync(0xffffffffu, v, o);
    if (lane == 0) out[row] = v + bfc[0];
}

// ---------------- launch ----------------
extern "C" void kernel_launch(void* const* d_in, const int* in_sizes, int n_in,
                              void* d_out, int out_size) {
    const float* x_seq   = (const float*)d_in[0];
    const int*   ei      = (const int*)d_in[1];
    const float* Wg      = (const float*)d_in[2];
    const float* att_src = (const float*)d_in[3];
    const float* att_dst = (const float*)d_in[4];
    const float* bias_g  = (const float*)d_in[5];
    const float* W_ih    = (const float*)d_in[6];
    const float* W_hh    = (const float*)d_in[7];
    const float* b_ih    = (const float*)d_in[8];
    const float* b_hh    = (const float*)d_in[9];
    const float* W_fc    = (const float*)d_in[10];
    const float* b_fc    = (const float*)d_in[11];
    float* out = (float*)d_out;

    void *p_cnt, *p_h, *p_hh, *p_hl, *p_sph, *p_spl, *p_gi, *p_gh;
    void *p_wih_h, *p_wih_l, *p_whh_h, *p_whh_l;
    cudaGetSymbolAddress(&p_cnt, d_cnt);
    cudaGetSymbolAddress(&p_h, d_h);
    cudaGetSymbolAddress(&p_hh, d_hh);
    cudaGetSymbolAddress(&p_hl, d_hl);
    cudaGetSymbolAddress(&p_sph, d_sph);
    cudaGetSymbolAddress(&p_spl, d_spl);
    cudaGetSymbolAddress(&p_gi, d_gi);
    cudaGetSymbolAddress(&p_gh, d_gh);
    cudaGetSymbolAddress(&p_wih_h, d_wih_h);
    cudaGetSymbolAddress(&p_wih_l, d_wih_l);
    cudaGetSymbolAddress(&p_whh_h, d_whh_h);
    cudaGetSymbolAddress(&p_whh_l, d_whh_l);

    cudaFuncSetAttribute(k_mma, cudaFuncAttributeMaxDynamicSharedMemorySize,
                         MMA_SMEM);

    cudaMemsetAsync(p_cnt, 0, NN * sizeof(int));
    cudaMemsetAsync(p_h, 0, (size_t)NN * HD * sizeof(float));
    cudaMemsetAsync(p_hh, 0, (size_t)NN * HD * sizeof(unsigned short));
    cudaMemsetAsync(p_hl, 0, (size_t)NN * HD * sizeof(unsigned short));

    k_wconv<<<(H3 * HD + 255) / 256, 256>>>(W_ih, W_hh);
    k_hist<<<(ET + 255) / 256, 256>>>(ei);
    k_scan<<<1, 1024>>>();
    k_scatter<<<(ET + 255) / 256, 256>>>(ei);

    dim3 mgrid((NN + 127) / 128, 3, 2);
    for (int t = 0; t < SEQL; t++) {
        k_xp<<<(NN + 1) / 2, 256>>>(x_seq + (size_t)t * NN * FIN, Wg,
                                    att_src, att_dst);
        k_gat<<<(NN + 7) / 8, 256>>>(bias_g);
        k_mma<<<mgrid, 256, MMA_SMEM>>>(
            (const uint4*)p_sph, (const uint4*)p_spl,
            (const uint4*)p_wih_h, (const uint4*)p_wih_l, b_ih, (float*)p_gi,
            (const uint4*)p_hh, (const uint4*)p_hl,
            (const uint4*)p_whh_h, (const uint4*)p_whh_l, b_hh, (float*)p_gh,
            NN);
        k_gru<<<(NN * HD / 4 + 255) / 256, 256>>>();
    }

    k_fc<<<(NN + 7) / 8, 256>>>(W_fc, b_fc, out);
}